// round 2
// baseline (speedup 1.0000x reference)
#include <cuda_runtime.h>
#include <math.h>

// Problem dims
#define BB 8
#define SS 2048
#define DD 768
#define EE 768
#define BSROWS (BB * SS)   // 16384

// Scratch (device globals — no allocation)
__device__ float g_Q[(size_t)BSROWS * EE];
__device__ float g_K[(size_t)BSROWS * EE];
__device__ float g_V[(size_t)BSROWS * EE];
__device__ float g_P[(size_t)BB * SS * SS];   // sim, then exp(sim - rowmax)
__device__ float g_invL[BSROWS];

// ---------------------------------------------------------------------------
// Tiled SGEMM core: 128x128 block tile, BK=8, 256 threads, 8x8 register tile,
// DOUBLE-BUFFERED shared memory (one __syncthreads per k-slab).
// TRANS_B=false: B is [K,N] row-major (NN).
// TRANS_B=true : B is [N,K] row-major (NT, i.e. C = A * B^T).
// EPI: 0 = plain, 1 = multiply by alpha, 2 = multiply row i by rowScale[row].
// Requires M%128==0, N%128==0, K%8==0 (true for all our shapes).
// ---------------------------------------------------------------------------
template<bool TRANS_B, int EPI>
__device__ __forceinline__ void gemm_body(
    const float* __restrict__ A, const float* __restrict__ Bm,
    float* __restrict__ C, int M, int N, int K,
    float alpha, const float* __restrict__ rowScale)
{
    __shared__ float As[2][8][128];
    __shared__ float Bs[2][8][128];

    const int tid  = threadIdx.x;
    const int row0 = blockIdx.y * 128;
    const int col0 = blockIdx.x * 128;

    // A tile loaders: 2 threads per row, 4 consecutive k's each (float4)
    const int arow = tid >> 1;            // 0..127
    const int acol = (tid & 1) << 2;      // 0 or 4
    const float* Aptr = A + (size_t)(row0 + arow) * K + acol;

    // B tile loaders
    const float* Bptr;
    int brow = 0, bcol = 0, bk = 0, bn = 0;
    if (TRANS_B) {
        brow = tid >> 1;                  // n index 0..127
        bcol = (tid & 1) << 2;            // k offset 0 or 4
        Bptr = Bm + (size_t)(col0 + brow) * K + bcol;
    } else {
        bk = tid >> 5;                    // 0..7
        bn = (tid & 31) << 2;             // 0..124
        Bptr = Bm + (size_t)bk * N + col0 + bn;
    }

    // compute-thread mapping: 16x16 threads, each 8x8 outputs
    const int tx = tid & 15;
    const int ty = tid >> 4;
    const int mb = ty * 8;
    const int nb = tx * 8;

    float acc[8][8];
#pragma unroll
    for (int i = 0; i < 8; i++)
#pragma unroll
        for (int j = 0; j < 8; j++) acc[i][j] = 0.f;

    const int nk = K / 8;

    // --- prologue: fill buffer 0 ---
    {
        const float4 av = *reinterpret_cast<const float4*>(Aptr);
        const float4 bv = *reinterpret_cast<const float4*>(Bptr);
        Aptr += 8;
        Bptr += TRANS_B ? (size_t)8 : (size_t)8 * N;
        As[0][acol + 0][arow] = av.x;
        As[0][acol + 1][arow] = av.y;
        As[0][acol + 2][arow] = av.z;
        As[0][acol + 3][arow] = av.w;
        if (TRANS_B) {
            Bs[0][bcol + 0][brow] = bv.x;
            Bs[0][bcol + 1][brow] = bv.y;
            Bs[0][bcol + 2][brow] = bv.z;
            Bs[0][bcol + 3][brow] = bv.w;
        } else {
            *reinterpret_cast<float4*>(&Bs[0][bk][bn]) = bv;
        }
    }
    __syncthreads();

    for (int kt = 0; kt < nk; kt++) {
        const int cur = kt & 1;
        const int nxt = cur ^ 1;
        const bool has_next = (kt + 1) < nk;

        // issue next slab's global loads early (overlap with compute below)
        float4 av, bv;
        if (has_next) {
            av = *reinterpret_cast<const float4*>(Aptr);
            bv = *reinterpret_cast<const float4*>(Bptr);
            Aptr += 8;
            Bptr += TRANS_B ? (size_t)8 : (size_t)8 * N;
        }

        // compute on current buffer
#pragma unroll
        for (int k = 0; k < 8; k++) {
            const float4 a0 = *reinterpret_cast<const float4*>(&As[cur][k][mb]);
            const float4 a1 = *reinterpret_cast<const float4*>(&As[cur][k][mb + 4]);
            const float4 b0 = *reinterpret_cast<const float4*>(&Bs[cur][k][nb]);
            const float4 b1 = *reinterpret_cast<const float4*>(&Bs[cur][k][nb + 4]);
            const float a[8] = {a0.x, a0.y, a0.z, a0.w, a1.x, a1.y, a1.z, a1.w};
            const float b[8] = {b0.x, b0.y, b0.z, b0.w, b1.x, b1.y, b1.z, b1.w};
#pragma unroll
            for (int i = 0; i < 8; i++)
#pragma unroll
                for (int j = 0; j < 8; j++)
                    acc[i][j] += a[i] * b[j];
        }

        // store next slab into the idle buffer; single barrier per iteration
        if (has_next) {
            As[nxt][acol + 0][arow] = av.x;
            As[nxt][acol + 1][arow] = av.y;
            As[nxt][acol + 2][arow] = av.z;
            As[nxt][acol + 3][arow] = av.w;
            if (TRANS_B) {
                Bs[nxt][bcol + 0][brow] = bv.x;
                Bs[nxt][bcol + 1][brow] = bv.y;
                Bs[nxt][bcol + 2][brow] = bv.z;
                Bs[nxt][bcol + 3][brow] = bv.w;
            } else {
                *reinterpret_cast<float4*>(&Bs[nxt][bk][bn]) = bv;
            }
            __syncthreads();
        }
    }

    // epilogue
#pragma unroll
    for (int i = 0; i < 8; i++) {
        float scale = 1.f;
        if (EPI == 1) scale = alpha;
        if (EPI == 2) scale = rowScale[row0 + mb + i];
        float4 o0, o1;
        o0.x = acc[i][0] * scale; o0.y = acc[i][1] * scale;
        o0.z = acc[i][2] * scale; o0.w = acc[i][3] * scale;
        o1.x = acc[i][4] * scale; o1.y = acc[i][5] * scale;
        o1.z = acc[i][6] * scale; o1.w = acc[i][7] * scale;
        float* cp = C + (size_t)(row0 + mb + i) * N + col0 + nb;
        *reinterpret_cast<float4*>(cp)     = o0;
        *reinterpret_cast<float4*>(cp + 4) = o1;
    }
}

// ---------------------------------------------------------------------------
// Kernel 1: fused QKV projections.  z = 0/1/2 selects Wq/Wk/Wv and Q/K/V out.
// ---------------------------------------------------------------------------
__global__ void __launch_bounds__(256, 2)
qkv_kernel(const float* __restrict__ X,
           const float* __restrict__ Wq,
           const float* __restrict__ Wk,
           const float* __restrict__ Wv)
{
    const int z = blockIdx.z;
    const float* W = (z == 0) ? Wq : ((z == 1) ? Wk : Wv);
    float* Cz      = (z == 0) ? g_Q : ((z == 1) ? g_K : g_V);
    gemm_body<false, 0>(X, W, Cz, BSROWS, EE, DD, 1.f, nullptr);
}

// ---------------------------------------------------------------------------
// Kernel 2: sim = Q @ K^T * (1/sqrt(768)), per batch.
// ---------------------------------------------------------------------------
__global__ void __launch_bounds__(256, 2)
sim_kernel()
{
    const int b = blockIdx.z;
    const float alpha = 0.036084391824351615f;   // 1/sqrt(768)
    gemm_body<true, 1>(g_Q + (size_t)b * SS * EE,
                       g_K + (size_t)b * SS * EE,
                       g_P + (size_t)b * SS * SS,
                       SS, SS, EE, alpha, nullptr);
}

// ---------------------------------------------------------------------------
// Kernel 3: row softmax (numerator in place + 1/denominator).
// One block per row (2048 elements, 256 threads, 2 float4 each).
// ---------------------------------------------------------------------------
__global__ void __launch_bounds__(256)
softmax_kernel()
{
    const size_t row = blockIdx.x;
    float* p = g_P + row * SS;
    const int t = threadIdx.x;

    float4 u0 = reinterpret_cast<const float4*>(p)[t];
    float4 u1 = reinterpret_cast<const float4*>(p)[t + 256];

    float m = fmaxf(fmaxf(fmaxf(u0.x, u0.y), fmaxf(u0.z, u0.w)),
                    fmaxf(fmaxf(u1.x, u1.y), fmaxf(u1.z, u1.w)));
#pragma unroll
    for (int o = 16; o > 0; o >>= 1)
        m = fmaxf(m, __shfl_xor_sync(0xffffffffu, m, o));

    __shared__ float smax[8];
    __shared__ float ssum[8];
    if ((t & 31) == 0) smax[t >> 5] = m;
    __syncthreads();
    float bm = smax[0];
#pragma unroll
    for (int j = 1; j < 8; j++) bm = fmaxf(bm, smax[j]);

    u0.x = __expf(u0.x - bm); u0.y = __expf(u0.y - bm);
    u0.z = __expf(u0.z - bm); u0.w = __expf(u0.w - bm);
    u1.x = __expf(u1.x - bm); u1.y = __expf(u1.y - bm);
    u1.z = __expf(u1.z - bm); u1.w = __expf(u1.w - bm);

    float s = (u0.x + u0.y) + (u0.z + u0.w) + (u1.x + u1.y) + (u1.z + u1.w);
#pragma unroll
    for (int o = 16; o > 0; o >>= 1)
        s += __shfl_xor_sync(0xffffffffu, s, o);
    if ((t & 31) == 0) ssum[t >> 5] = s;
    __syncthreads();
    float tot = 0.f;
#pragma unroll
    for (int j = 0; j < 8; j++) tot += ssum[j];

    reinterpret_cast<float4*>(p)[t]       = u0;
    reinterpret_cast<float4*>(p)[t + 256] = u1;
    if (t == 0) g_invL[row] = 1.f / tot;
}

// ---------------------------------------------------------------------------
// Kernel 4: out = P~ @ V scaled per-row by 1/L, per batch.
// ---------------------------------------------------------------------------
__global__ void __launch_bounds__(256, 2)
out_kernel(float* __restrict__ out)
{
    const int b = blockIdx.z;
    gemm_body<false, 2>(g_P + (size_t)b * SS * SS,
                        g_V + (size_t)b * SS * EE,
                        out + (size_t)b * SS * EE,
                        SS, EE, SS, 1.f, g_invL + (size_t)b * SS);
}

// ---------------------------------------------------------------------------
extern "C" void kernel_launch(void* const* d_in, const int* in_sizes, int n_in,
                              void* d_out, int out_size)
{
    (void)in_sizes; (void)n_in; (void)out_size;
    const float* X  = (const float*)d_in[0];
    const float* Wq = (const float*)d_in[1];
    const float* Wk = (const float*)d_in[2];
    const float* Wv = (const float*)d_in[3];
    float* out = (float*)d_out;

    dim3 blk(256);
    qkv_kernel<<<dim3(EE / 128, BSROWS / 128, 3), blk>>>(X, Wq, Wk, Wv);
    sim_kernel<<<dim3(SS / 128, SS / 128, BB), blk>>>();
    softmax_kernel<<<BSROWS, 256>>>();
    out_kernel<<<dim3(EE / 128, SS / 128, BB), blk>>>(out);
}

// round 4
// speedup vs baseline: 1.1569x; 1.1569x over previous
#include <cuda_runtime.h>
#include <math.h>
#include <stdint.h>

// Problem dims
#define BB 8
#define SS 2048
#define DD 768
#define EE 768
#define BSROWS (BB * SS)   // 16384

// Scratch (device globals — no allocation)
__device__ float g_Q[(size_t)BSROWS * EE];
__device__ float g_K[(size_t)BSROWS * EE];
__device__ float g_V[(size_t)BSROWS * EE];
__device__ float g_P[(size_t)BB * SS * SS];   // sim, then exp(sim - rowmax)
__device__ float g_invL[BSROWS];

// ---------------------------------------------------------------------------
// TF32 helpers
// ---------------------------------------------------------------------------
__device__ __forceinline__ uint32_t f2tf32(float x) {
    uint32_t u;
    asm("cvt.rna.tf32.f32 %0, %1;" : "=r"(u) : "f"(x));
    return u;
}

__device__ __forceinline__ void mma_tf32(float* c, const uint32_t* a, const uint32_t* b) {
    asm volatile(
        "mma.sync.aligned.m16n8k8.row.col.f32.tf32.tf32.f32 "
        "{%0,%1,%2,%3}, {%4,%5,%6,%7}, {%8,%9}, {%0,%1,%2,%3};"
        : "+f"(c[0]), "+f"(c[1]), "+f"(c[2]), "+f"(c[3])
        : "r"(a[0]), "r"(a[1]), "r"(a[2]), "r"(a[3]),
          "r"(b[0]), "r"(b[1]));
}

// ---------------------------------------------------------------------------
// Tensor-core TF32 GEMM: C[M,N] = op(A[M,K] x B), 128x128 CTA tile, BK=16,
// 256 threads (8 warps as 2x4), warp tile 64x32 via m16n8k8 atoms.
// Smem holds fragment-permuted tiles so frag loads are vectorized:
//   A:  [buf][kstep(2)][atom_m(8)][lane(32)][j(4)]   -> LDS.128 per m-atom
//   B:  [buf][kstep(2)][atom_n(16)][lane(32)][j(2)]  -> LDS.64  per n-atom
// Fragment spec (m16n8k8.row.col, g=lane>>2, t=lane&3):
//   a0=A[g][t] a1=A[g+8][t] a2=A[g][t+4] a3=A[g+8][t+4]
//   b0=B[t][g] b1=B[t+4][g];  c rows {g,g+8}, cols {2t,2t+1}
// TRANS_B=false: B is [K,N] row-major (NN). TRANS_B=true: B is [N,K] (NT).
// EPI: 0 plain, 1 alpha, 2 per-row rowScale.
// Requires M%128==0, N%128==0, K%16==0.
// ---------------------------------------------------------------------------
template<bool TRANS_B, int EPI>
__device__ __forceinline__ void gemm_tc(
    const float* __restrict__ A, const float* __restrict__ Bm,
    float* __restrict__ C, int M, int N, int K,
    float alpha, const float* __restrict__ rowScale)
{
    __shared__ float As[2][2048];   // 2 bufs x (2*8*32*4)
    __shared__ float Bs[2][2048];   // 2 bufs x (2*16*32*2)

    const int tid  = threadIdx.x;
    const int lane = tid & 31;
    const int wid  = tid >> 5;
    const int warp_m = wid >> 2;   // 0..1
    const int warp_n = wid & 3;    // 0..3
    const int row0 = blockIdx.y * 128;
    const int col0 = blockIdx.x * 128;

    // ---- staging index precompute ----
    // A: thread handles rows aR and aR+64, k-quad akq (k = 4*akq + i, i<4)
    const int aR  = tid >> 2;          // 0..63
    const int akq = tid & 3;
    const float* Aptr0 = A + (size_t)(row0 + aR)      * K + akq * 4;
    const float* Aptr1 = A + (size_t)(row0 + aR + 64) * K + akq * 4;
    // dest base: ks*1024 + atom_m*128 + (Rm&7)*16 + (Rm>>3) + 2*ajk, elems at +4*i
    const int aks = akq >> 1, ajk = akq & 1;
    const int Rm0 = aR & 15;
    const int adst0 = aks * 1024 + (aR >> 4) * 128 + (Rm0 & 7) * 16 + (Rm0 >> 3) + 2 * ajk;
    const int Rm1 = (aR + 64) & 15;
    const int adst1 = aks * 1024 + ((aR + 64) >> 4) * 128 + (Rm1 & 7) * 16 + (Rm1 >> 3) + 2 * ajk;

    const float* Bptr0;
    const float* Bptr1;
    int bdst0 = 0, bdst1 = 0;          // NT: full dest base; NN handled per-elem
    int bk_nn = 0;
    if (TRANS_B) {
        const int n   = tid >> 2;      // 0..63 (and n+64)
        const int bkq = tid & 3;
        Bptr0 = Bm + (size_t)(col0 + n)      * K + bkq * 4;
        Bptr1 = Bm + (size_t)(col0 + n + 64) * K + bkq * 4;
        const int bks = bkq >> 1, bjk = bkq & 1;
        bdst0 = bks * 1024 + (n >> 3) * 64 + (n & 7) * 8 + bjk;
        bdst1 = bks * 1024 + ((n + 64) >> 3) * 64 + ((n + 64) & 7) * 8 + bjk;
    } else {
        bk_nn = tid >> 5;              // 0..7 (and +8)
        const int nq = tid & 31;
        Bptr0 = Bm + (size_t)bk_nn * N + col0 + nq * 4;
        Bptr1 = Bm + (size_t)(bk_nn + 8) * N + col0 + nq * 4;
    }

    float acc[4][4][4];
#pragma unroll
    for (int am = 0; am < 4; am++)
#pragma unroll
        for (int bn = 0; bn < 4; bn++)
#pragma unroll
            for (int j = 0; j < 4; j++) acc[am][bn][j] = 0.f;

    const int nk = K / 16;

    auto store_slab = [&](int buf, float4 av0, float4 av1, float4 bv0, float4 bv1) {
        float* ad = As[buf];
        ad[adst0 + 0]  = __uint_as_float(f2tf32(av0.x));
        ad[adst0 + 4]  = __uint_as_float(f2tf32(av0.y));
        ad[adst0 + 8]  = __uint_as_float(f2tf32(av0.z));
        ad[adst0 + 12] = __uint_as_float(f2tf32(av0.w));
        ad[adst1 + 0]  = __uint_as_float(f2tf32(av1.x));
        ad[adst1 + 4]  = __uint_as_float(f2tf32(av1.y));
        ad[adst1 + 8]  = __uint_as_float(f2tf32(av1.z));
        ad[adst1 + 12] = __uint_as_float(f2tf32(av1.w));
        float* bd = Bs[buf];
        if (TRANS_B) {
            bd[bdst0 + 0] = __uint_as_float(f2tf32(bv0.x));
            bd[bdst0 + 2] = __uint_as_float(f2tf32(bv0.y));
            bd[bdst0 + 4] = __uint_as_float(f2tf32(bv0.z));
            bd[bdst0 + 6] = __uint_as_float(f2tf32(bv0.w));
            bd[bdst1 + 0] = __uint_as_float(f2tf32(bv1.x));
            bd[bdst1 + 2] = __uint_as_float(f2tf32(bv1.y));
            bd[bdst1 + 4] = __uint_as_float(f2tf32(bv1.z));
            bd[bdst1 + 6] = __uint_as_float(f2tf32(bv1.w));
        } else {
            const int nq = tid & 31;
            const float bb0[4] = {bv0.x, bv0.y, bv0.z, bv0.w};
            const float bb1[4] = {bv1.x, bv1.y, bv1.z, bv1.w};
            {
                const int k = bk_nn;               // 0..7 -> ks=0
                const int c = k & 3, j = (k >> 2) & 1;
#pragma unroll
                for (int i = 0; i < 4; i++) {
                    const int ni = nq * 4 + i;
                    bd[(ni >> 3) * 64 + (ni & 7) * 8 + c * 2 + j] =
                        __uint_as_float(f2tf32(bb0[i]));
                }
            }
            {
                const int k = bk_nn + 8;           // 8..15 -> ks=1
                const int c = k & 3, j = (k >> 2) & 1;
#pragma unroll
                for (int i = 0; i < 4; i++) {
                    const int ni = nq * 4 + i;
                    bd[1024 + (ni >> 3) * 64 + (ni & 7) * 8 + c * 2 + j] =
                        __uint_as_float(f2tf32(bb1[i]));
                }
            }
        }
    };

    // ---- prologue: slab 0 into buffer 0 ----
    {
        float4 av0 = *reinterpret_cast<const float4*>(Aptr0);
        float4 av1 = *reinterpret_cast<const float4*>(Aptr1);
        float4 bv0 = *reinterpret_cast<const float4*>(Bptr0);
        float4 bv1 = *reinterpret_cast<const float4*>(Bptr1);
        Aptr0 += 16; Aptr1 += 16;
        if (TRANS_B) { Bptr0 += 16; Bptr1 += 16; }
        else         { Bptr0 += (size_t)16 * N; Bptr1 += (size_t)16 * N; }
        store_slab(0, av0, av1, bv0, bv1);
    }
    __syncthreads();

    for (int kt = 0; kt < nk; kt++) {
        const int cur = kt & 1;
        const bool has_next = (kt + 1) < nk;

        float4 av0, av1, bv0, bv1;
        if (has_next) {
            av0 = *reinterpret_cast<const float4*>(Aptr0);
            av1 = *reinterpret_cast<const float4*>(Aptr1);
            bv0 = *reinterpret_cast<const float4*>(Bptr0);
            bv1 = *reinterpret_cast<const float4*>(Bptr1);
            Aptr0 += 16; Aptr1 += 16;
            if (TRANS_B) { Bptr0 += 16; Bptr1 += 16; }
            else         { Bptr0 += (size_t)16 * N; Bptr1 += (size_t)16 * N; }
        }

        // ---- compute on current buffer: 2 k-steps x 16 atoms/warp ----
        const float* aSb = As[cur] + (warp_m * 4) * 128 + lane * 4;
        const float* bSb = Bs[cur] + (warp_n * 4) * 64 + lane * 2;
#pragma unroll
        for (int ks = 0; ks < 2; ks++) {
            uint32_t af[4][4];
            uint32_t bf[4][2];
#pragma unroll
            for (int am = 0; am < 4; am++) {
                const float4 v = *reinterpret_cast<const float4*>(aSb + ks * 1024 + am * 128);
                af[am][0] = __float_as_uint(v.x);
                af[am][1] = __float_as_uint(v.y);
                af[am][2] = __float_as_uint(v.z);
                af[am][3] = __float_as_uint(v.w);
            }
#pragma unroll
            for (int bn = 0; bn < 4; bn++) {
                const float2 v = *reinterpret_cast<const float2*>(bSb + ks * 1024 + bn * 64);
                bf[bn][0] = __float_as_uint(v.x);
                bf[bn][1] = __float_as_uint(v.y);
            }
#pragma unroll
            for (int am = 0; am < 4; am++)
#pragma unroll
                for (int bn = 0; bn < 4; bn++)
                    mma_tf32(acc[am][bn], af[am], bf[bn]);
        }

        if (has_next) {
            store_slab(cur ^ 1, av0, av1, bv0, bv1);
            __syncthreads();
        }
    }

    // ---- epilogue ----
#pragma unroll
    for (int am = 0; am < 4; am++) {
        const int r = row0 + warp_m * 64 + am * 16 + (lane >> 2);
        float s0 = 1.f, s1 = 1.f;
        if (EPI == 1) { s0 = alpha; s1 = alpha; }
        if (EPI == 2) { s0 = rowScale[r]; s1 = rowScale[r + 8]; }
#pragma unroll
        for (int bn = 0; bn < 4; bn++) {
            const int ccol = col0 + warp_n * 32 + bn * 8 + 2 * (lane & 3);
            float2 lo, hi;
            lo.x = acc[am][bn][0] * s0; lo.y = acc[am][bn][1] * s0;
            hi.x = acc[am][bn][2] * s1; hi.y = acc[am][bn][3] * s1;
            *reinterpret_cast<float2*>(C + (size_t)r * N + ccol)       = lo;
            *reinterpret_cast<float2*>(C + (size_t)(r + 8) * N + ccol) = hi;
        }
    }
}

// ---------------------------------------------------------------------------
// Kernel 1: fused QKV projections (NN).
// ---------------------------------------------------------------------------
__global__ void __launch_bounds__(256, 2)
qkv_kernel(const float* __restrict__ X,
           const float* __restrict__ Wq,
           const float* __restrict__ Wk,
           const float* __restrict__ Wv)
{
    const int z = blockIdx.z;
    const float* W = (z == 0) ? Wq : ((z == 1) ? Wk : Wv);
    float* Cz      = (z == 0) ? g_Q : ((z == 1) ? g_K : g_V);
    gemm_tc<false, 0>(X, W, Cz, BSROWS, EE, DD, 1.f, nullptr);
}

// ---------------------------------------------------------------------------
// Kernel 2: sim = Q @ K^T * (1/sqrt(768)), per batch (NT).
// ---------------------------------------------------------------------------
__global__ void __launch_bounds__(256, 2)
sim_kernel()
{
    const int b = blockIdx.z;
    const float alpha = 0.036084391824351615f;   // 1/sqrt(768)
    gemm_tc<true, 1>(g_Q + (size_t)b * SS * EE,
                     g_K + (size_t)b * SS * EE,
                     g_P + (size_t)b * SS * SS,
                     SS, SS, EE, alpha, nullptr);
}

// ---------------------------------------------------------------------------
// Kernel 3: row softmax (numerator in place + 1/denominator).
// ---------------------------------------------------------------------------
__global__ void __launch_bounds__(256)
softmax_kernel()
{
    const size_t row = blockIdx.x;
    float* p = g_P + row * SS;
    const int t = threadIdx.x;

    float4 u0 = reinterpret_cast<const float4*>(p)[t];
    float4 u1 = reinterpret_cast<const float4*>(p)[t + 256];

    float m = fmaxf(fmaxf(fmaxf(u0.x, u0.y), fmaxf(u0.z, u0.w)),
                    fmaxf(fmaxf(u1.x, u1.y), fmaxf(u1.z, u1.w)));
#pragma unroll
    for (int o = 16; o > 0; o >>= 1)
        m = fmaxf(m, __shfl_xor_sync(0xffffffffu, m, o));

    __shared__ float smax[8];
    __shared__ float ssum[8];
    if ((t & 31) == 0) smax[t >> 5] = m;
    __syncthreads();
    float bm = smax[0];
#pragma unroll
    for (int j = 1; j < 8; j++) bm = fmaxf(bm, smax[j]);

    u0.x = __expf(u0.x - bm); u0.y = __expf(u0.y - bm);
    u0.z = __expf(u0.z - bm); u0.w = __expf(u0.w - bm);
    u1.x = __expf(u1.x - bm); u1.y = __expf(u1.y - bm);
    u1.z = __expf(u1.z - bm); u1.w = __expf(u1.w - bm);

    float s = (u0.x + u0.y) + (u0.z + u0.w) + (u1.x + u1.y) + (u1.z + u1.w);
#pragma unroll
    for (int o = 16; o > 0; o >>= 1)
        s += __shfl_xor_sync(0xffffffffu, s, o);
    if ((t & 31) == 0) ssum[t >> 5] = s;
    __syncthreads();
    float tot = 0.f;
#pragma unroll
    for (int j = 0; j < 8; j++) tot += ssum[j];

    reinterpret_cast<float4*>(p)[t]       = u0;
    reinterpret_cast<float4*>(p)[t + 256] = u1;
    if (t == 0) g_invL[row] = 1.f / tot;
}

// ---------------------------------------------------------------------------
// Kernel 4: out = P~ @ V scaled per-row by 1/L, per batch (NN).
// ---------------------------------------------------------------------------
__global__ void __launch_bounds__(256, 2)
out_kernel(float* __restrict__ out)
{
    const int b = blockIdx.z;
    gemm_tc<false, 2>(g_P + (size_t)b * SS * SS,
                      g_V + (size_t)b * SS * EE,
                      out + (size_t)b * SS * EE,
                      SS, EE, SS, 1.f, g_invL + (size_t)b * SS);
}

// ---------------------------------------------------------------------------
extern "C" void kernel_launch(void* const* d_in, const int* in_sizes, int n_in,
                              void* d_out, int out_size)
{
    (void)in_sizes; (void)n_in; (void)out_size;
    const float* X  = (const float*)d_in[0];
    const float* Wq = (const float*)d_in[1];
    const float* Wk = (const float*)d_in[2];
    const float* Wv = (const float*)d_in[3];
    float* out = (float*)d_out;

    dim3 blk(256);
    qkv_kernel<<<dim3(EE / 128, BSROWS / 128, 3), blk>>>(X, Wq, Wk, Wv);
    sim_kernel<<<dim3(SS / 128, SS / 128, BB), blk>>>();
    softmax_kernel<<<BSROWS, 256>>>();
    out_kernel<<<dim3(EE / 128, SS / 128, BB), blk>>>(out);
}

// round 8
// speedup vs baseline: 2.9374x; 2.5389x over previous
#include <cuda_runtime.h>
#include <stdint.h>
#include <math.h>

// ---------------------------------------------------------------------------
// Problem dims
// ---------------------------------------------------------------------------
#define BB 8
#define SS 2048
#define DD 768
#define EE 768
#define BSROWS (BB * SS)   // 16384

// ---------------------------------------------------------------------------
// Scratch (device globals — no allocation)
// ---------------------------------------------------------------------------
__device__ float g_Xr[(size_t)BSROWS * DD];       // tf32-rounded inputs
__device__ float g_Wt[(size_t)3 * EE * DD];       // W^T, tf32-rounded: [z][e][d]
__device__ float g_Q [(size_t)BSROWS * EE];       // tf32-rounded
__device__ float g_K [(size_t)BSROWS * EE];       // tf32-rounded
__device__ float g_V [(size_t)BSROWS * EE];       // tf32-rounded
__device__ float g_Vt[(size_t)BB * EE * SS];      // V^T per batch: [b][e][s]
__device__ float g_P [(size_t)BB * SS * SS];      // sim, then tf32 exp(sim-max)
__device__ float g_invL[BSROWS];

__device__ __forceinline__ uint32_t f2tf32(float x) {
    uint32_t u;
    asm("cvt.rna.tf32.f32 %0, %1;" : "=r"(u) : "f"(x));
    return u;
}
__device__ __forceinline__ uint32_t smem_u32(const void* p) {
    uint32_t a;
    asm("{ .reg .u64 t; cvta.to.shared.u64 t, %1; cvt.u32.u64 %0, t; }" : "=r"(a) : "l"(p));
    return a;
}
__device__ __forceinline__ void mma_tf32(float* c, const uint32_t* a, const uint32_t* b) {
    asm volatile(
        "mma.sync.aligned.m16n8k8.row.col.f32.tf32.tf32.f32 "
        "{%0,%1,%2,%3}, {%4,%5,%6,%7}, {%8,%9}, {%0,%1,%2,%3};"
        : "+f"(c[0]), "+f"(c[1]), "+f"(c[2]), "+f"(c[3])
        : "r"(a[0]), "r"(a[1]), "r"(a[2]), "r"(a[3]),
          "r"(b[0]), "r"(b[1]));
}
#define CP_ASYNC16(dst, src) \
    asm volatile("cp.async.cg.shared.global [%0], [%1], 16;" :: "r"(dst), "l"(src) : "memory")
#define CP_COMMIT() asm volatile("cp.async.commit_group;" ::: "memory")
#define CP_WAIT2()  asm volatile("cp.async.wait_group 2;" ::: "memory")
#define CP_WAIT0()  asm volatile("cp.async.wait_group 0;" ::: "memory")

// ---------------------------------------------------------------------------
// SMEM geometry: 4-stage ring; per stage A tile + B tile.
// Tile = 128 rows x 16 k-floats, stored with 20-float (80B) row stride.
// (g*20+t) mod 32 covers 32 distinct banks -> all fragment LDS.32 conflict-free.
// ---------------------------------------------------------------------------
#define ROWF 20                       // floats per smem row (16 data + 4 pad)
#define TILEF (128 * ROWF)            // 2560 floats per tile
#define STAGEF (2 * TILEF)            // A + B
#define STAGES 4
#define SMEM_FLOATS (STAGES * STAGEF) // 20480 floats = 81920 B
#define EPIL_STRIDE 132               // epilogue staging row stride (floats)

// ---------------------------------------------------------------------------
// TF32 mma.sync GEMM: C[128x128] = A[128xK] x B[128xK]^T (both K-major, lda=ldb=K)
// 128 threads, warps 2x2, warp tile 64x64 (4 m-atoms x 8 n-atoms of m16n8k8).
// cp.async 4-stage pipeline, BK=16 (2 k-steps per slab).
// Operands must already be tf32-rounded in gmem.
// EPI 0: qkv (C select by z, tf32-round output)
// EPI 1: sim (scale alpha)   EPI 2: out (scale invL per row)
// ---------------------------------------------------------------------------
template<int EPI>
__global__ void __launch_bounds__(128, 2)
tc2_gemm(const float* __restrict__ A0, const float* __restrict__ B0,
         float* __restrict__ C0, float* __restrict__ C1, float* __restrict__ C2,
         const float* __restrict__ invL, int K, int ldc,
         size_t aStride, size_t bStride, size_t cStride, float alpha)
{
    extern __shared__ float sm[];
    const uint32_t sb = smem_u32(sm);
    const int tid  = threadIdx.x;
    const int wid  = tid >> 5;
    const int lane = tid & 31;
    const int wm = wid >> 1, wn = wid & 1;
    const int g = lane >> 2, t = lane & 3;
    const int z = blockIdx.z;
    const int row0 = blockIdx.y * 128;
    const int col0 = blockIdx.x * 128;

    const float* A = A0 + (size_t)z * aStride;
    const float* B = B0 + (size_t)z * bStride;
    float* C;
    if (EPI == 0) C = (z == 0) ? C0 : ((z == 1) ? C1 : C2);
    else          C = C0 + (size_t)z * cStride;

    // cp.async mapping: thread copies rows cr, cr+32, cr+64, cr+96; k-quad cq
    const int cr = tid >> 2;
    const int cq = tid & 3;

    const int nslab = K / 16;

    auto load_stage = [&](int s, int kt) {
        const uint32_t abase = sb + (uint32_t)(s * STAGEF) * 4;
        const uint32_t bbase = abase + (uint32_t)TILEF * 4;
        const float* ag = A + (size_t)(row0 + cr) * K + kt * 16 + cq * 4;
        const float* bg = B + (size_t)(col0 + cr) * K + kt * 16 + cq * 4;
#pragma unroll
        for (int i = 0; i < 4; i++) {
            const uint32_t soff = (uint32_t)((cr + i * 32) * ROWF + cq * 4) * 4;
            CP_ASYNC16(abase + soff, ag + (size_t)(i * 32) * K);
            CP_ASYNC16(bbase + soff, bg + (size_t)(i * 32) * K);
        }
    };

    float acc[4][8][4];
#pragma unroll
    for (int am = 0; am < 4; am++)
#pragma unroll
        for (int bn = 0; bn < 8; bn++)
#pragma unroll
            for (int j = 0; j < 4; j++) acc[am][bn][j] = 0.f;

    // prologue: 3 stages in flight
#pragma unroll
    for (int s = 0; s < 3; s++) {
        load_stage(s, s);
        CP_COMMIT();
    }

    for (int kt = 0; kt < nslab; kt++) {
        CP_WAIT2();                    // stage kt&3 complete
        __syncthreads();               // all warps done with stage (kt-1)&3
        if (kt + 3 < nslab)
            load_stage((kt + 3) & 3, kt + 3);
        CP_COMMIT();                   // uniform group accounting

        const uint32_t* sA = reinterpret_cast<const uint32_t*>(sm + (kt & 3) * STAGEF);
        const uint32_t* sB = sA + TILEF;

#pragma unroll
        for (int ks = 0; ks < 2; ks++) {
            uint32_t a[4][4], b[8][2];
#pragma unroll
            for (int am = 0; am < 4; am++) {
                const int base = (wm * 64 + am * 16 + g) * ROWF + ks * 8 + t;
                a[am][0] = sA[base];
                a[am][1] = sA[base + 8 * ROWF];
                a[am][2] = sA[base + 4];
                a[am][3] = sA[base + 8 * ROWF + 4];
            }
#pragma unroll
            for (int bn = 0; bn < 8; bn++) {
                const int base = (wn * 64 + bn * 8 + g) * ROWF + ks * 8 + t;
                b[bn][0] = sB[base];
                b[bn][1] = sB[base + 4];
            }
#pragma unroll
            for (int am = 0; am < 4; am++)
#pragma unroll
                for (int bn = 0; bn < 8; bn++)
                    mma_tf32(acc[am][bn], a[am], b[bn]);
        }
    }

    // ---- epilogue: stage (scaled) in smem, then coalesced stores ----
    CP_WAIT0();
    __syncthreads();

#pragma unroll
    for (int am = 0; am < 4; am++) {
        const int r = wm * 64 + am * 16 + g;
        float s0 = 1.f, s1 = 1.f;
        if (EPI == 1) { s0 = alpha; s1 = alpha; }
        if (EPI == 2) {
            s0 = invL[(size_t)z * SS + row0 + r];
            s1 = invL[(size_t)z * SS + row0 + r + 8];
        }
#pragma unroll
        for (int bn = 0; bn < 8; bn++) {
            const int c = wn * 64 + bn * 8 + 2 * t;
            float v0 = acc[am][bn][0] * s0, v1 = acc[am][bn][1] * s0;
            float v2 = acc[am][bn][2] * s1, v3 = acc[am][bn][3] * s1;
            if (EPI == 0) {
                v0 = __uint_as_float(f2tf32(v0));
                v1 = __uint_as_float(f2tf32(v1));
                v2 = __uint_as_float(f2tf32(v2));
                v3 = __uint_as_float(f2tf32(v3));
            }
            sm[r * EPIL_STRIDE + c]           = v0;
            sm[r * EPIL_STRIDE + c + 1]       = v1;
            sm[(r + 8) * EPIL_STRIDE + c]     = v2;
            sm[(r + 8) * EPIL_STRIDE + c + 1] = v3;
        }
    }
    __syncthreads();

#pragma unroll 4
    for (int it = 0; it < 32; it++) {
        const int r = it * 4 + wid;
        const float4 v = *reinterpret_cast<const float4*>(sm + r * EPIL_STRIDE + lane * 4);
        *reinterpret_cast<float4*>(C + (size_t)(row0 + r) * ldc + col0 + lane * 4) = v;
    }
}

// ---------------------------------------------------------------------------
// Prep kernels
// ---------------------------------------------------------------------------
__global__ void round_x_kernel(const float* __restrict__ X)
{
    const size_t n4 = (size_t)BSROWS * DD / 4;
    for (size_t i = (size_t)blockIdx.x * blockDim.x + threadIdx.x; i < n4;
         i += (size_t)gridDim.x * blockDim.x) {
        float4 v = reinterpret_cast<const float4*>(X)[i];
        v.x = __uint_as_float(f2tf32(v.x));
        v.y = __uint_as_float(f2tf32(v.y));
        v.z = __uint_as_float(f2tf32(v.z));
        v.w = __uint_as_float(f2tf32(v.w));
        reinterpret_cast<float4*>(g_Xr)[i] = v;
    }
}

// W[d][e] -> Wt[z][e][d], tf32-rounded.  grid (24,24,3), block (32,8)
__global__ void wtrans_kernel(const float* __restrict__ Wq,
                              const float* __restrict__ Wk,
                              const float* __restrict__ Wv)
{
    __shared__ float t[32][33];
    const int z = blockIdx.z;
    const float* W = (z == 0) ? Wq : ((z == 1) ? Wk : Wv);
    float* Wt = g_Wt + (size_t)z * EE * DD;
    const int bx = blockIdx.x * 32, by = blockIdx.y * 32;
    const int tx = threadIdx.x, ty = threadIdx.y;
#pragma unroll
    for (int i = 0; i < 32; i += 8)
        t[ty + i][tx] = W[(size_t)(by + ty + i) * EE + bx + tx];
    __syncthreads();
#pragma unroll
    for (int i = 0; i < 32; i += 8)
        Wt[(size_t)(bx + ty + i) * DD + by + tx] = __uint_as_float(f2tf32(t[tx][ty + i]));
}

// V[b][s][e] -> Vt[b][e][s].  grid (24, 64, 8), block (32,8)
__global__ void vtrans_kernel()
{
    __shared__ float t[32][33];
    const int b = blockIdx.z;
    const float* Vin = g_V + (size_t)b * SS * EE;
    float* Vout = g_Vt + (size_t)b * EE * SS;
    const int bx = blockIdx.x * 32;   // e
    const int by = blockIdx.y * 32;   // s
    const int tx = threadIdx.x, ty = threadIdx.y;
#pragma unroll
    for (int i = 0; i < 32; i += 8)
        t[ty + i][tx] = Vin[(size_t)(by + ty + i) * EE + bx + tx];
    __syncthreads();
#pragma unroll
    for (int i = 0; i < 32; i += 8)
        Vout[(size_t)(bx + ty + i) * SS + by + tx] = t[tx][ty + i];
}

// ---------------------------------------------------------------------------
// Row softmax: in-place tf32-rounded exp(sim - rowmax) + 1/sum
// ---------------------------------------------------------------------------
__global__ void __launch_bounds__(256)
softmax_kernel()
{
    const size_t row = blockIdx.x;
    float* p = g_P + row * SS;
    const int t = threadIdx.x;

    float4 u0 = reinterpret_cast<const float4*>(p)[t];
    float4 u1 = reinterpret_cast<const float4*>(p)[t + 256];

    float m = fmaxf(fmaxf(fmaxf(u0.x, u0.y), fmaxf(u0.z, u0.w)),
                    fmaxf(fmaxf(u1.x, u1.y), fmaxf(u1.z, u1.w)));
#pragma unroll
    for (int o = 16; o > 0; o >>= 1)
        m = fmaxf(m, __shfl_xor_sync(0xffffffffu, m, o));

    __shared__ float smax[8];
    __shared__ float ssum[8];
    if ((t & 31) == 0) smax[t >> 5] = m;
    __syncthreads();
    float bm = smax[0];
#pragma unroll
    for (int j = 1; j < 8; j++) bm = fmaxf(bm, smax[j]);

    u0.x = __expf(u0.x - bm); u0.y = __expf(u0.y - bm);
    u0.z = __expf(u0.z - bm); u0.w = __expf(u0.w - bm);
    u1.x = __expf(u1.x - bm); u1.y = __expf(u1.y - bm);
    u1.z = __expf(u1.z - bm); u1.w = __expf(u1.w - bm);

    float s = (u0.x + u0.y) + (u0.z + u0.w) + (u1.x + u1.y) + (u1.z + u1.w);
#pragma unroll
    for (int o = 16; o > 0; o >>= 1)
        s += __shfl_xor_sync(0xffffffffu, s, o);
    if ((t & 31) == 0) ssum[t >> 5] = s;
    __syncthreads();
    float tot = 0.f;
#pragma unroll
    for (int j = 0; j < 8; j++) tot += ssum[j];

    u0.x = __uint_as_float(f2tf32(u0.x)); u0.y = __uint_as_float(f2tf32(u0.y));
    u0.z = __uint_as_float(f2tf32(u0.z)); u0.w = __uint_as_float(f2tf32(u0.w));
    u1.x = __uint_as_float(f2tf32(u1.x)); u1.y = __uint_as_float(f2tf32(u1.y));
    u1.z = __uint_as_float(f2tf32(u1.z)); u1.w = __uint_as_float(f2tf32(u1.w));

    reinterpret_cast<float4*>(p)[t]       = u0;
    reinterpret_cast<float4*>(p)[t + 256] = u1;
    if (t == 0) g_invL[row] = 1.f / tot;
}

// ---------------------------------------------------------------------------
// Host
// ---------------------------------------------------------------------------
#define SMEM_BYTES (SMEM_FLOATS * 4)   // 81920

extern "C" void kernel_launch(void* const* d_in, const int* in_sizes, int n_in,
                              void* d_out, int out_size)
{
    (void)in_sizes; (void)n_in; (void)out_size;
    const float* X  = (const float*)d_in[0];
    const float* Wq = (const float*)d_in[1];
    const float* Wk = (const float*)d_in[2];
    const float* Wv = (const float*)d_in[3];
    float* out = (float*)d_out;

    void *pXr, *pWt, *pQ, *pK, *pV, *pVt, *pP, *pL;
    cudaGetSymbolAddress(&pXr, g_Xr);
    cudaGetSymbolAddress(&pWt, g_Wt);
    cudaGetSymbolAddress(&pQ,  g_Q);
    cudaGetSymbolAddress(&pK,  g_K);
    cudaGetSymbolAddress(&pV,  g_V);
    cudaGetSymbolAddress(&pVt, g_Vt);
    cudaGetSymbolAddress(&pP,  g_P);
    cudaGetSymbolAddress(&pL,  g_invL);

    cudaFuncSetAttribute(tc2_gemm<0>, cudaFuncAttributeMaxDynamicSharedMemorySize, SMEM_BYTES);
    cudaFuncSetAttribute(tc2_gemm<1>, cudaFuncAttributeMaxDynamicSharedMemorySize, SMEM_BYTES);
    cudaFuncSetAttribute(tc2_gemm<2>, cudaFuncAttributeMaxDynamicSharedMemorySize, SMEM_BYTES);

    const float alpha = 0.036084391824351615f;   // 1/sqrt(768)

    round_x_kernel<<<3072, 256>>>(X);
    wtrans_kernel<<<dim3(24, 24, 3), dim3(32, 8)>>>(Wq, Wk, Wv);

    // qkv: A = Xr (shared across z), B = Wt[z], C = Q/K/V
    tc2_gemm<0><<<dim3(EE / 128, BSROWS / 128, 3), 128, SMEM_BYTES>>>(
        (const float*)pXr, (const float*)pWt,
        (float*)pQ, (float*)pK, (float*)pV, nullptr,
        DD, EE, 0, (size_t)EE * DD, 0, 1.f);

    vtrans_kernel<<<dim3(24, 64, 8), dim3(32, 8)>>>();

    // sim: A = Q[b], B = K[b], C = P[b], scale alpha
    tc2_gemm<1><<<dim3(SS / 128, SS / 128, BB), 128, SMEM_BYTES>>>(
        (const float*)pQ, (const float*)pK,
        (float*)pP, nullptr, nullptr, nullptr,
        EE, SS, (size_t)SS * EE, (size_t)SS * EE, (size_t)SS * SS, alpha);

    softmax_kernel<<<BSROWS, 256>>>();

    // out: A = P[b], B = Vt[b], C = out[b], scale invL
    tc2_gemm<2><<<dim3(EE / 128, SS / 128, BB), 128, SMEM_BYTES>>>(
        (const float*)pP, (const float*)pVt,
        out, nullptr, nullptr, (const float*)pL,
        SS, EE, (size_t)SS * SS, (size_t)SS * EE, (size_t)SS * EE, 1.f);
}

// round 10
// speedup vs baseline: 5.5705x; 1.8964x over previous
#include <cuda_runtime.h>
#include <cuda_fp16.h>
#include <stdint.h>

// ---------------------------------------------------------------------------
// Problem dims
// ---------------------------------------------------------------------------
#define BB 8
#define SS 2048
#define DD 768
#define EE 768
#define BSROWS (BB * SS)   // 16384

// ---------------------------------------------------------------------------
// Scratch (device globals — no allocation).  All operands fp16, accum fp32.
// ---------------------------------------------------------------------------
__device__ __half g_Xh [(size_t)BSROWS * DD];     // fp16-rounded inputs
__device__ __half g_Wth[(size_t)3 * EE * DD];     // W^T fp16: [z][e][d]
__device__ __half g_Qh [(size_t)BSROWS * EE];
__device__ __half g_Kh [(size_t)BSROWS * EE];
__device__ __half g_Vh [(size_t)BSROWS * EE];
__device__ __half g_Vth[(size_t)BB * EE * SS];    // V^T per batch: [b][e][s]
__device__ __half g_Ph [(size_t)BB * SS * SS];    // sim, then exp(sim-max)
__device__ float  g_invL[BSROWS];

__device__ __forceinline__ uint32_t smem_u32(const void* p) {
    uint32_t a;
    asm("{ .reg .u64 t; cvta.to.shared.u64 t, %1; cvt.u32.u64 %0, t; }" : "=r"(a) : "l"(p));
    return a;
}
// bitcast __half2 -> uint32
__device__ __forceinline__ uint32_t h2_to_u32(__half2 h) {
    union { __half2 h2; uint32_t u; } cvt;
    cvt.h2 = h;
    return cvt.u;
}
// fp16 MMA, fp32 accumulate.  Fragment order (m16n8k16.row.col):
// a0=A[g][2t:2t+1]  a1=A[g+8][2t:2t+1]  a2=A[g][2t+8:2t+9]  a3=A[g+8][2t+8:2t+9]
// b0=B[g][2t:2t+1]  b1=B[g][2t+8:2t+9]   (B stored [n][k] row-major)
// c{0,1}=rows g cols 2t,2t+1 ; c{2,3}=rows g+8
__device__ __forceinline__ void mma_f16(float* c, const uint32_t* a, const uint32_t* b) {
    asm volatile(
        "mma.sync.aligned.m16n8k16.row.col.f32.f16.f16.f32 "
        "{%0,%1,%2,%3}, {%4,%5,%6,%7}, {%8,%9}, {%0,%1,%2,%3};"
        : "+f"(c[0]), "+f"(c[1]), "+f"(c[2]), "+f"(c[3])
        : "r"(a[0]), "r"(a[1]), "r"(a[2]), "r"(a[3]),
          "r"(b[0]), "r"(b[1]));
}
#define CP_ASYNC16(dst, src) \
    asm volatile("cp.async.cg.shared.global [%0], [%1], 16;" :: "r"(dst), "l"(src) : "memory")
#define CP_COMMIT() asm volatile("cp.async.commit_group;" ::: "memory")
#define CP_WAIT2()  asm volatile("cp.async.wait_group 2;" ::: "memory")
#define CP_WAIT0()  asm volatile("cp.async.wait_group 0;" ::: "memory")

// ---------------------------------------------------------------------------
// SMEM geometry: 4-stage ring.  Tile = 128 rows x 16 halves (32B) + 16B pad
// -> 12 words/row.  Fragment LDS banks: (12g + t) mod 32 covers all 32.
// ---------------------------------------------------------------------------
#define ROWW 12                       // 32-bit words per smem row
#define TILEW (128 * ROWW)            // 1536 words per tile
#define STAGEW (2 * TILEW)            // A + B
#define STAGES 4
#define ESH 136                       // epilogue half-stride (halves)
#define ESF 132                       // epilogue float-stride (floats)
#define SMEM_BYTES 67584              // max(ring 49152, f32 staging 67584)

// ---------------------------------------------------------------------------
// FP16 mma.sync GEMM: C[128x128] = A[128xK] x B[128xK]^T, K-major halves.
// 128 threads, warps 2x2, warp tile 64x64 (4 m-atoms x 8 n-atoms m16n8k16).
// cp.async 4-stage ring, BK=16 (one k-step per slab).
// EPI 0: qkv -> half C (select by z)  EPI 1: sim -> half P (scale alpha)
// EPI 2: out -> float C (scale invL per row)
// ---------------------------------------------------------------------------
template<int EPI>
__global__ void __launch_bounds__(128, 2)
h_gemm(const __half* __restrict__ A0, const __half* __restrict__ B0,
       void* __restrict__ C0, void* __restrict__ C1, void* __restrict__ C2,
       const float* __restrict__ invL, int K, int ldc,
       size_t aStride, size_t bStride, size_t cStride, float alpha)
{
    extern __shared__ uint32_t smw[];
    const uint32_t sb = smem_u32(smw);
    const int tid  = threadIdx.x;
    const int wid  = tid >> 5;
    const int lane = tid & 31;
    const int wm = wid >> 1, wn = wid & 1;
    const int g = lane >> 2, t = lane & 3;
    const int z = blockIdx.z;
    const int row0 = blockIdx.y * 128;
    const int col0 = blockIdx.x * 128;

    const __half* A = A0 + (size_t)z * aStride;
    const __half* B = B0 + (size_t)z * bStride;

    // cp.async: thread copies rows cr, cr+64; 16B chunk cq of each 32B row
    const int cr = tid >> 1;
    const int cq = tid & 1;
    const int nslab = K / 16;

    auto load_stage = [&](int s, int kt) {
        const uint32_t abase = sb + (uint32_t)(s * STAGEW) * 4;
        const uint32_t bbase = abase + (uint32_t)TILEW * 4;
        const __half* ag = A + (size_t)(row0 + cr) * K + kt * 16 + cq * 8;
        const __half* bg = B + (size_t)(col0 + cr) * K + kt * 16 + cq * 8;
#pragma unroll
        for (int i = 0; i < 2; i++) {
            const uint32_t soff = (uint32_t)((cr + i * 64) * ROWW + cq * 4) * 4;
            CP_ASYNC16(abase + soff, ag + (size_t)(i * 64) * K);
            CP_ASYNC16(bbase + soff, bg + (size_t)(i * 64) * K);
        }
    };

    float acc[4][8][4];
#pragma unroll
    for (int am = 0; am < 4; am++)
#pragma unroll
        for (int bn = 0; bn < 8; bn++)
#pragma unroll
            for (int j = 0; j < 4; j++) acc[am][bn][j] = 0.f;

#pragma unroll
    for (int s = 0; s < 3; s++) {
        load_stage(s, s);
        CP_COMMIT();
    }

    for (int kt = 0; kt < nslab; kt++) {
        CP_WAIT2();
        __syncthreads();
        if (kt + 3 < nslab)
            load_stage((kt + 3) & 3, kt + 3);
        CP_COMMIT();

        const uint32_t* sA = smw + (kt & 3) * STAGEW;
        const uint32_t* sB = sA + TILEW;

        uint32_t a[4][4], b[8][2];
#pragma unroll
        for (int am = 0; am < 4; am++) {
            const int base = (wm * 64 + am * 16 + g) * ROWW + t;
            a[am][0] = sA[base];
            a[am][1] = sA[base + 8 * ROWW];
            a[am][2] = sA[base + 4];
            a[am][3] = sA[base + 8 * ROWW + 4];
        }
#pragma unroll
        for (int bn = 0; bn < 8; bn++) {
            const int base = (wn * 64 + bn * 8 + g) * ROWW + t;
            b[bn][0] = sB[base];
            b[bn][1] = sB[base + 4];
        }
#pragma unroll
        for (int am = 0; am < 4; am++)
#pragma unroll
            for (int bn = 0; bn < 8; bn++)
                mma_f16(acc[am][bn], a[am], b[bn]);
    }

    CP_WAIT0();
    __syncthreads();

    if (EPI == 2) {
        // float output staging
        float* smf = reinterpret_cast<float*>(smw);
        float* C = (float*)C0 + (size_t)z * cStride;
#pragma unroll
        for (int am = 0; am < 4; am++) {
            const int r = wm * 64 + am * 16 + g;
            const float s0 = invL[(size_t)z * SS + row0 + r];
            const float s1 = invL[(size_t)z * SS + row0 + r + 8];
#pragma unroll
            for (int bn = 0; bn < 8; bn++) {
                const int c = wn * 64 + bn * 8 + 2 * t;
                smf[r * ESF + c]           = acc[am][bn][0] * s0;
                smf[r * ESF + c + 1]       = acc[am][bn][1] * s0;
                smf[(r + 8) * ESF + c]     = acc[am][bn][2] * s1;
                smf[(r + 8) * ESF + c + 1] = acc[am][bn][3] * s1;
            }
        }
        __syncthreads();
#pragma unroll 4
        for (int it = 0; it < 32; it++) {
            const int r = it * 4 + wid;
            const float4 v = *reinterpret_cast<const float4*>(smf + r * ESF + lane * 4);
            *reinterpret_cast<float4*>(C + (size_t)(row0 + r) * ldc + col0 + lane * 4) = v;
        }
    } else {
        // half output staging
        __half* smh = reinterpret_cast<__half*>(smw);
        __half* C;
        if (EPI == 0) C = (z == 0) ? (__half*)C0 : ((z == 1) ? (__half*)C1 : (__half*)C2);
        else          C = (__half*)C0 + (size_t)z * cStride;
        const float s = (EPI == 1) ? alpha : 1.f;
#pragma unroll
        for (int am = 0; am < 4; am++) {
            const int r = wm * 64 + am * 16 + g;
#pragma unroll
            for (int bn = 0; bn < 8; bn++) {
                const int c = wn * 64 + bn * 8 + 2 * t;
                const __half2 lo = __floats2half2_rn(acc[am][bn][0] * s, acc[am][bn][1] * s);
                const __half2 hi = __floats2half2_rn(acc[am][bn][2] * s, acc[am][bn][3] * s);
                *reinterpret_cast<__half2*>(smh + r * ESH + c)       = lo;
                *reinterpret_cast<__half2*>(smh + (r + 8) * ESH + c) = hi;
            }
        }
        __syncthreads();
#pragma unroll 4
        for (int it = 0; it < 16; it++) {
            const int r = it * 8 + (tid >> 4);
            const int l16 = tid & 15;
            const uint4 v = *reinterpret_cast<const uint4*>(smh + r * ESH + l16 * 8);
            *reinterpret_cast<uint4*>(C + (size_t)(row0 + r) * ldc + col0 + l16 * 8) = v;
        }
    }
}

// ---------------------------------------------------------------------------
// Prep kernels
// ---------------------------------------------------------------------------
__global__ void round_x_kernel(const float* __restrict__ X)
{
    const size_t n8 = (size_t)BSROWS * DD / 8;
    for (size_t i = (size_t)blockIdx.x * blockDim.x + threadIdx.x; i < n8;
         i += (size_t)gridDim.x * blockDim.x) {
        const float4 u = reinterpret_cast<const float4*>(X)[2 * i];
        const float4 v = reinterpret_cast<const float4*>(X)[2 * i + 1];
        uint4 o;
        o.x = h2_to_u32(__floats2half2_rn(u.x, u.y));
        o.y = h2_to_u32(__floats2half2_rn(u.z, u.w));
        o.z = h2_to_u32(__floats2half2_rn(v.x, v.y));
        o.w = h2_to_u32(__floats2half2_rn(v.z, v.w));
        reinterpret_cast<uint4*>(g_Xh)[i] = o;
    }
}

// W[d][e] -> Wth[z][e][d] (half).  grid (24,24,3), block (32,8)
__global__ void wtrans_kernel(const float* __restrict__ Wq,
                              const float* __restrict__ Wk,
                              const float* __restrict__ Wv)
{
    __shared__ float t[32][33];
    const int z = blockIdx.z;
    const float* W = (z == 0) ? Wq : ((z == 1) ? Wk : Wv);
    __half* Wt = g_Wth + (size_t)z * EE * DD;
    const int bx = blockIdx.x * 32, by = blockIdx.y * 32;
    const int tx = threadIdx.x, ty = threadIdx.y;
#pragma unroll
    for (int i = 0; i < 32; i += 8)
        t[ty + i][tx] = W[(size_t)(by + ty + i) * EE + bx + tx];
    __syncthreads();
#pragma unroll
    for (int i = 0; i < 32; i += 8)
        Wt[(size_t)(bx + ty + i) * DD + by + tx] = __float2half_rn(t[tx][ty + i]);
}

// V[b][s][e] -> Vt[b][e][s] (half).  grid (24, 64, 8), block (32,8)
__global__ void vtrans_kernel()
{
    __shared__ __half t[32][33];
    const int b = blockIdx.z;
    const __half* Vin = g_Vh + (size_t)b * SS * EE;
    __half* Vout = g_Vth + (size_t)b * EE * SS;
    const int bx = blockIdx.x * 32;   // e
    const int by = blockIdx.y * 32;   // s
    const int tx = threadIdx.x, ty = threadIdx.y;
#pragma unroll
    for (int i = 0; i < 32; i += 8)
        t[ty + i][tx] = Vin[(size_t)(by + ty + i) * EE + bx + tx];
    __syncthreads();
#pragma unroll
    for (int i = 0; i < 32; i += 8)
        Vout[(size_t)(bx + ty + i) * SS + by + tx] = t[tx][ty + i];
}

// ---------------------------------------------------------------------------
// Row softmax on half P: in-place exp(sim - rowmax) + 1/sum (float)
// One block per row; 256 threads x 8 halves.
// ---------------------------------------------------------------------------
__global__ void __launch_bounds__(256)
softmax_kernel()
{
    const size_t row = blockIdx.x;
    __half* p = g_Ph + row * SS;
    const int t = threadIdx.x;

    uint4 raw = reinterpret_cast<const uint4*>(p)[t];
    __half2* hp = reinterpret_cast<__half2*>(&raw);
    float2 f0 = __half22float2(hp[0]);
    float2 f1 = __half22float2(hp[1]);
    float2 f2 = __half22float2(hp[2]);
    float2 f3 = __half22float2(hp[3]);

    float m = fmaxf(fmaxf(fmaxf(f0.x, f0.y), fmaxf(f1.x, f1.y)),
                    fmaxf(fmaxf(f2.x, f2.y), fmaxf(f3.x, f3.y)));
#pragma unroll
    for (int o = 16; o > 0; o >>= 1)
        m = fmaxf(m, __shfl_xor_sync(0xffffffffu, m, o));

    __shared__ float smax[8];
    __shared__ float ssum[8];
    if ((t & 31) == 0) smax[t >> 5] = m;
    __syncthreads();
    float bm = smax[0];
#pragma unroll
    for (int j = 1; j < 8; j++) bm = fmaxf(bm, smax[j]);

    f0.x = __expf(f0.x - bm); f0.y = __expf(f0.y - bm);
    f1.x = __expf(f1.x - bm); f1.y = __expf(f1.y - bm);
    f2.x = __expf(f2.x - bm); f2.y = __expf(f2.y - bm);
    f3.x = __expf(f3.x - bm); f3.y = __expf(f3.y - bm);

    float s = (f0.x + f0.y) + (f1.x + f1.y) + (f2.x + f2.y) + (f3.x + f3.y);
#pragma unroll
    for (int o = 16; o > 0; o >>= 1)
        s += __shfl_xor_sync(0xffffffffu, s, o);
    if ((t & 31) == 0) ssum[t >> 5] = s;
    __syncthreads();
    float tot = 0.f;
#pragma unroll
    for (int j = 0; j < 8; j++) tot += ssum[j];

    hp[0] = __floats2half2_rn(f0.x, f0.y);
    hp[1] = __floats2half2_rn(f1.x, f1.y);
    hp[2] = __floats2half2_rn(f2.x, f2.y);
    hp[3] = __floats2half2_rn(f3.x, f3.y);
    reinterpret_cast<uint4*>(p)[t] = raw;
    if (t == 0) g_invL[row] = 1.f / tot;
}

// ---------------------------------------------------------------------------
// Host
// ---------------------------------------------------------------------------
extern "C" void kernel_launch(void* const* d_in, const int* in_sizes, int n_in,
                              void* d_out, int out_size)
{
    (void)in_sizes; (void)n_in; (void)out_size;
    const float* X  = (const float*)d_in[0];
    const float* Wq = (const float*)d_in[1];
    const float* Wk = (const float*)d_in[2];
    const float* Wv = (const float*)d_in[3];
    float* out = (float*)d_out;

    void *pXh, *pWth, *pQh, *pKh, *pVh, *pVth, *pPh, *pL;
    cudaGetSymbolAddress(&pXh,  g_Xh);
    cudaGetSymbolAddress(&pWth, g_Wth);
    cudaGetSymbolAddress(&pQh,  g_Qh);
    cudaGetSymbolAddress(&pKh,  g_Kh);
    cudaGetSymbolAddress(&pVh,  g_Vh);
    cudaGetSymbolAddress(&pVth, g_Vth);
    cudaGetSymbolAddress(&pPh,  g_Ph);
    cudaGetSymbolAddress(&pL,   g_invL);

    cudaFuncSetAttribute(h_gemm<0>, cudaFuncAttributeMaxDynamicSharedMemorySize, SMEM_BYTES);
    cudaFuncSetAttribute(h_gemm<1>, cudaFuncAttributeMaxDynamicSharedMemorySize, SMEM_BYTES);
    cudaFuncSetAttribute(h_gemm<2>, cudaFuncAttributeMaxDynamicSharedMemorySize, SMEM_BYTES);

    const float alpha = 0.036084391824351615f;   // 1/sqrt(768)

    round_x_kernel<<<3072, 256>>>(X);
    wtrans_kernel<<<dim3(24, 24, 3), dim3(32, 8)>>>(Wq, Wk, Wv);

    // qkv: A = Xh (shared across z), B = Wth[z], C = Qh/Kh/Vh (half)
    h_gemm<0><<<dim3(EE / 128, BSROWS / 128, 3), 128, SMEM_BYTES>>>(
        (const __half*)pXh, (const __half*)pWth,
        pQh, pKh, pVh, nullptr,
        DD, EE, 0, (size_t)EE * DD, 0, 1.f);

    vtrans_kernel<<<dim3(24, 64, 8), dim3(32, 8)>>>();

    // sim: A = Qh[b], B = Kh[b], C = Ph[b] (half), scale alpha
    h_gemm<1><<<dim3(SS / 128, SS / 128, BB), 128, SMEM_BYTES>>>(
        (const __half*)pQh, (const __half*)pKh,
        pPh, nullptr, nullptr, nullptr,
        EE, SS, (size_t)SS * EE, (size_t)SS * EE, (size_t)SS * SS, alpha);

    softmax_kernel<<<BSROWS, 256>>>();

    // out: A = Ph[b], B = Vth[b], C = out[b] (float), scale invL
    h_gemm<2><<<dim3(EE / 128, SS / 128, BB), 128, SMEM_BYTES>>>(
        (const __half*)pPh, (const __half*)pVth,
        out, nullptr, nullptr, (const float*)pL,
        SS, EE, (size_t)SS * SS, (size_t)SS * EE, (size_t)SS * EE, 1.f);
}

// round 11
// speedup vs baseline: 5.9404x; 1.0664x over previous
#include <cuda_runtime.h>
#include <cuda_fp16.h>
#include <stdint.h>

// ---------------------------------------------------------------------------
// Problem dims
// ---------------------------------------------------------------------------
#define BB 8
#define SS 2048
#define DD 768
#define EE 768
#define BSROWS (BB * SS)   // 16384

// ---------------------------------------------------------------------------
// Scratch (device globals — no allocation).  All operands fp16, accum fp32.
// Algebra: sim = X·G·X^T with G = Wq·Wk^T·alpha.  We compute H = G^T = Wk·Wq^T
// (x alpha), R = X·H^T? no: R[a][m] = sum_i X[a][i]·H[m][i]  (NT form, B=H),
// sim[a][b] = sum_m R[a][m]·X[b][m]  (NT form, B=X).  K never materialized.
// ---------------------------------------------------------------------------
__device__ __half g_Xh [(size_t)BSROWS * DD];     // fp16 inputs
__device__ __half g_Wqh[(size_t)DD * EE];         // Wq fp16 (natural layout)
__device__ __half g_Wkh[(size_t)DD * EE];         // Wk fp16 (natural layout)
__device__ __half g_B2 [(size_t)2 * EE * DD];     // [0]=H (alpha-folded), [1]=Wv^T
__device__ __half g_Rh [(size_t)BSROWS * EE];     // R = X·H^T-form
__device__ __half g_Vh [(size_t)BSROWS * EE];
__device__ __half g_Vth[(size_t)BB * EE * SS];    // V^T per batch: [b][e][s]
__device__ __half g_Ph [(size_t)BB * SS * SS];    // sim, then exp(sim-max)
__device__ float  g_invL[BSROWS];

__device__ __forceinline__ uint32_t smem_u32(const void* p) {
    uint32_t a;
    asm("{ .reg .u64 t; cvta.to.shared.u64 t, %1; cvt.u32.u64 %0, t; }" : "=r"(a) : "l"(p));
    return a;
}
__device__ __forceinline__ uint32_t h2_to_u32(__half2 h) {
    union { __half2 h2; uint32_t u; } cvt;
    cvt.h2 = h;
    return cvt.u;
}
// fp16 MMA, fp32 accumulate (m16n8k16.row.col), fragment order as validated.
__device__ __forceinline__ void mma_f16(float* c, const uint32_t* a, const uint32_t* b) {
    asm volatile(
        "mma.sync.aligned.m16n8k16.row.col.f32.f16.f16.f32 "
        "{%0,%1,%2,%3}, {%4,%5,%6,%7}, {%8,%9}, {%0,%1,%2,%3};"
        : "+f"(c[0]), "+f"(c[1]), "+f"(c[2]), "+f"(c[3])
        : "r"(a[0]), "r"(a[1]), "r"(a[2]), "r"(a[3]),
          "r"(b[0]), "r"(b[1]));
}
#define CP_ASYNC16(dst, src) \
    asm volatile("cp.async.cg.shared.global [%0], [%1], 16;" :: "r"(dst), "l"(src) : "memory")
#define CP_COMMIT() asm volatile("cp.async.commit_group;" ::: "memory")
#define CP_WAIT2()  asm volatile("cp.async.wait_group 2;" ::: "memory")
#define CP_WAIT0()  asm volatile("cp.async.wait_group 0;" ::: "memory")

#define ROWW 12
#define TILEW (128 * ROWW)
#define STAGEW (2 * TILEW)
#define ESH 136
#define ESF 132
#define SMEM_BYTES 67584

// ---------------------------------------------------------------------------
// FP16 mma.sync GEMM: C[128x128] = A[128xK] x B[128xK]^T, K-major halves.
// 128 threads, warps 2x2, warp tile 64x64, cp.async 4-stage ring, BK=16.
// EPI 0: half C select by z (C0/C1/C2), scale 1
// EPI 1: half C = C0 + z*cStride, scale alpha
// EPI 2: float C = C0 + z*cStride, scale invL per row
// ---------------------------------------------------------------------------
template<int EPI>
__global__ void __launch_bounds__(128, 2)
h_gemm(const __half* __restrict__ A0, const __half* __restrict__ B0,
       void* __restrict__ C0, void* __restrict__ C1, void* __restrict__ C2,
       const float* __restrict__ invL, int K, int ldc,
       size_t aStride, size_t bStride, size_t cStride, float alpha)
{
    extern __shared__ uint32_t smw[];
    const uint32_t sb = smem_u32(smw);
    const int tid  = threadIdx.x;
    const int wid  = tid >> 5;
    const int lane = tid & 31;
    const int wm = wid >> 1, wn = wid & 1;
    const int g = lane >> 2, t = lane & 3;
    const int z = blockIdx.z;
    const int row0 = blockIdx.y * 128;
    const int col0 = blockIdx.x * 128;

    const __half* A = A0 + (size_t)z * aStride;
    const __half* B = B0 + (size_t)z * bStride;

    const int cr = tid >> 1;
    const int cq = tid & 1;
    const int nslab = K / 16;

    auto load_stage = [&](int s, int kt) {
        const uint32_t abase = sb + (uint32_t)(s * STAGEW) * 4;
        const uint32_t bbase = abase + (uint32_t)TILEW * 4;
        const __half* ag = A + (size_t)(row0 + cr) * K + kt * 16 + cq * 8;
        const __half* bg = B + (size_t)(col0 + cr) * K + kt * 16 + cq * 8;
#pragma unroll
        for (int i = 0; i < 2; i++) {
            const uint32_t soff = (uint32_t)((cr + i * 64) * ROWW + cq * 4) * 4;
            CP_ASYNC16(abase + soff, ag + (size_t)(i * 64) * K);
            CP_ASYNC16(bbase + soff, bg + (size_t)(i * 64) * K);
        }
    };

    float acc[4][8][4];
#pragma unroll
    for (int am = 0; am < 4; am++)
#pragma unroll
        for (int bn = 0; bn < 8; bn++)
#pragma unroll
            for (int j = 0; j < 4; j++) acc[am][bn][j] = 0.f;

#pragma unroll
    for (int s = 0; s < 3; s++) {
        load_stage(s, s);
        CP_COMMIT();
    }

    for (int kt = 0; kt < nslab; kt++) {
        CP_WAIT2();
        __syncthreads();
        if (kt + 3 < nslab)
            load_stage((kt + 3) & 3, kt + 3);
        CP_COMMIT();

        const uint32_t* sA = smw + (kt & 3) * STAGEW;
        const uint32_t* sB = sA + TILEW;

        uint32_t a[4][4], b[8][2];
#pragma unroll
        for (int am = 0; am < 4; am++) {
            const int base = (wm * 64 + am * 16 + g) * ROWW + t;
            a[am][0] = sA[base];
            a[am][1] = sA[base + 8 * ROWW];
            a[am][2] = sA[base + 4];
            a[am][3] = sA[base + 8 * ROWW + 4];
        }
#pragma unroll
        for (int bn = 0; bn < 8; bn++) {
            const int base = (wn * 64 + bn * 8 + g) * ROWW + t;
            b[bn][0] = sB[base];
            b[bn][1] = sB[base + 4];
        }
#pragma unroll
        for (int am = 0; am < 4; am++)
#pragma unroll
            for (int bn = 0; bn < 8; bn++)
                mma_f16(acc[am][bn], a[am], b[bn]);
    }

    CP_WAIT0();
    __syncthreads();

    if (EPI == 2) {
        float* smf = reinterpret_cast<float*>(smw);
        float* C = (float*)C0 + (size_t)z * cStride;
#pragma unroll
        for (int am = 0; am < 4; am++) {
            const int r = wm * 64 + am * 16 + g;
            const float s0 = invL[(size_t)z * SS + row0 + r];
            const float s1 = invL[(size_t)z * SS + row0 + r + 8];
#pragma unroll
            for (int bn = 0; bn < 8; bn++) {
                const int c = wn * 64 + bn * 8 + 2 * t;
                smf[r * ESF + c]           = acc[am][bn][0] * s0;
                smf[r * ESF + c + 1]       = acc[am][bn][1] * s0;
                smf[(r + 8) * ESF + c]     = acc[am][bn][2] * s1;
                smf[(r + 8) * ESF + c + 1] = acc[am][bn][3] * s1;
            }
        }
        __syncthreads();
#pragma unroll 4
        for (int it = 0; it < 32; it++) {
            const int r = it * 4 + wid;
            const float4 v = *reinterpret_cast<const float4*>(smf + r * ESF + lane * 4);
            *reinterpret_cast<float4*>(C + (size_t)(row0 + r) * ldc + col0 + lane * 4) = v;
        }
    } else {
        __half* smh = reinterpret_cast<__half*>(smw);
        __half* C;
        if (EPI == 0) C = (z == 0) ? (__half*)C0 : ((z == 1) ? (__half*)C1 : (__half*)C2);
        else          C = (__half*)C0 + (size_t)z * cStride;
        const float s = (EPI == 1) ? alpha : 1.f;
#pragma unroll
        for (int am = 0; am < 4; am++) {
            const int r = wm * 64 + am * 16 + g;
#pragma unroll
            for (int bn = 0; bn < 8; bn++) {
                const int c = wn * 64 + bn * 8 + 2 * t;
                const __half2 lo = __floats2half2_rn(acc[am][bn][0] * s, acc[am][bn][1] * s);
                const __half2 hi = __floats2half2_rn(acc[am][bn][2] * s, acc[am][bn][3] * s);
                *reinterpret_cast<__half2*>(smh + r * ESH + c)       = lo;
                *reinterpret_cast<__half2*>(smh + (r + 8) * ESH + c) = hi;
            }
        }
        __syncthreads();
#pragma unroll 4
        for (int it = 0; it < 16; it++) {
            const int r = it * 8 + (tid >> 4);
            const int l16 = tid & 15;
            const uint4 v = *reinterpret_cast<const uint4*>(smh + r * ESH + l16 * 8);
            *reinterpret_cast<uint4*>(C + (size_t)(row0 + r) * ldc + col0 + l16 * 8) = v;
        }
    }
}

// ---------------------------------------------------------------------------
// Prep kernels
// ---------------------------------------------------------------------------
__global__ void round_x_kernel(const float* __restrict__ X)
{
    const size_t n8 = (size_t)BSROWS * DD / 8;
    for (size_t i = (size_t)blockIdx.x * blockDim.x + threadIdx.x; i < n8;
         i += (size_t)gridDim.x * blockDim.x) {
        const float4 u = reinterpret_cast<const float4*>(X)[2 * i];
        const float4 v = reinterpret_cast<const float4*>(X)[2 * i + 1];
        uint4 o;
        o.x = h2_to_u32(__floats2half2_rn(u.x, u.y));
        o.y = h2_to_u32(__floats2half2_rn(u.z, u.w));
        o.z = h2_to_u32(__floats2half2_rn(v.x, v.y));
        o.w = h2_to_u32(__floats2half2_rn(v.z, v.w));
        reinterpret_cast<uint4*>(g_Xh)[i] = o;
    }
}

// Round Wq, Wk to fp16 in natural [d][e] layout.
__global__ void round_w_kernel(const float* __restrict__ Wq,
                               const float* __restrict__ Wk)
{
    const size_t n8 = (size_t)DD * EE / 8;
    for (size_t i = (size_t)blockIdx.x * blockDim.x + threadIdx.x; i < n8;
         i += (size_t)gridDim.x * blockDim.x) {
        {
            const float4 u = reinterpret_cast<const float4*>(Wq)[2 * i];
            const float4 v = reinterpret_cast<const float4*>(Wq)[2 * i + 1];
            uint4 o;
            o.x = h2_to_u32(__floats2half2_rn(u.x, u.y));
            o.y = h2_to_u32(__floats2half2_rn(u.z, u.w));
            o.z = h2_to_u32(__floats2half2_rn(v.x, v.y));
            o.w = h2_to_u32(__floats2half2_rn(v.z, v.w));
            reinterpret_cast<uint4*>(g_Wqh)[i] = o;
        }
        {
            const float4 u = reinterpret_cast<const float4*>(Wk)[2 * i];
            const float4 v = reinterpret_cast<const float4*>(Wk)[2 * i + 1];
            uint4 o;
            o.x = h2_to_u32(__floats2half2_rn(u.x, u.y));
            o.y = h2_to_u32(__floats2half2_rn(u.z, u.w));
            o.z = h2_to_u32(__floats2half2_rn(v.x, v.y));
            o.w = h2_to_u32(__floats2half2_rn(v.z, v.w));
            reinterpret_cast<uint4*>(g_Wkh)[i] = o;
        }
    }
}

// Wv[d][e] -> g_B2[1][e][d] (half).  grid (24,24), block (32,8)
__global__ void wtrans_v_kernel(const float* __restrict__ Wv)
{
    __shared__ float t[32][33];
    __half* Wt = g_B2 + (size_t)EE * DD;
    const int bx = blockIdx.x * 32, by = blockIdx.y * 32;
    const int tx = threadIdx.x, ty = threadIdx.y;
#pragma unroll
    for (int i = 0; i < 32; i += 8)
        t[ty + i][tx] = Wv[(size_t)(by + ty + i) * EE + bx + tx];
    __syncthreads();
#pragma unroll
    for (int i = 0; i < 32; i += 8)
        Wt[(size_t)(bx + ty + i) * DD + by + tx] = __float2half_rn(t[tx][ty + i]);
}

// V[b][s][e] -> Vt[b][e][s] (half).  grid (24, 64, 8), block (32,8)
__global__ void vtrans_kernel()
{
    __shared__ __half t[32][33];
    const int b = blockIdx.z;
    const __half* Vin = g_Vh + (size_t)b * SS * EE;
    __half* Vout = g_Vth + (size_t)b * EE * SS;
    const int bx = blockIdx.x * 32;   // e
    const int by = blockIdx.y * 32;   // s
    const int tx = threadIdx.x, ty = threadIdx.y;
#pragma unroll
    for (int i = 0; i < 32; i += 8)
        t[ty + i][tx] = Vin[(size_t)(by + ty + i) * EE + bx + tx];
    __syncthreads();
#pragma unroll
    for (int i = 0; i < 32; i += 8)
        Vout[(size_t)(bx + ty + i) * SS + by + tx] = t[tx][ty + i];
}

// ---------------------------------------------------------------------------
// Row softmax on half P: in-place exp(sim - rowmax) + 1/sum (float)
// ---------------------------------------------------------------------------
__global__ void __launch_bounds__(256)
softmax_kernel()
{
    const size_t row = blockIdx.x;
    __half* p = g_Ph + row * SS;
    const int t = threadIdx.x;

    uint4 raw = reinterpret_cast<const uint4*>(p)[t];
    __half2* hp = reinterpret_cast<__half2*>(&raw);
    float2 f0 = __half22float2(hp[0]);
    float2 f1 = __half22float2(hp[1]);
    float2 f2 = __half22float2(hp[2]);
    float2 f3 = __half22float2(hp[3]);

    float m = fmaxf(fmaxf(fmaxf(f0.x, f0.y), fmaxf(f1.x, f1.y)),
                    fmaxf(fmaxf(f2.x, f2.y), fmaxf(f3.x, f3.y)));
#pragma unroll
    for (int o = 16; o > 0; o >>= 1)
        m = fmaxf(m, __shfl_xor_sync(0xffffffffu, m, o));

    __shared__ float smax[8];
    __shared__ float ssum[8];
    if ((t & 31) == 0) smax[t >> 5] = m;
    __syncthreads();
    float bm = smax[0];
#pragma unroll
    for (int j = 1; j < 8; j++) bm = fmaxf(bm, smax[j]);

    f0.x = __expf(f0.x - bm); f0.y = __expf(f0.y - bm);
    f1.x = __expf(f1.x - bm); f1.y = __expf(f1.y - bm);
    f2.x = __expf(f2.x - bm); f2.y = __expf(f2.y - bm);
    f3.x = __expf(f3.x - bm); f3.y = __expf(f3.y - bm);

    float s = (f0.x + f0.y) + (f1.x + f1.y) + (f2.x + f2.y) + (f3.x + f3.y);
#pragma unroll
    for (int o = 16; o > 0; o >>= 1)
        s += __shfl_xor_sync(0xffffffffu, s, o);
    if ((t & 31) == 0) ssum[t >> 5] = s;
    __syncthreads();
    float tot = 0.f;
#pragma unroll
    for (int j = 0; j < 8; j++) tot += ssum[j];

    hp[0] = __floats2half2_rn(f0.x, f0.y);
    hp[1] = __floats2half2_rn(f1.x, f1.y);
    hp[2] = __floats2half2_rn(f2.x, f2.y);
    hp[3] = __floats2half2_rn(f3.x, f3.y);
    reinterpret_cast<uint4*>(p)[t] = raw;
    if (t == 0) g_invL[row] = 1.f / tot;
}

// ---------------------------------------------------------------------------
// Host
// ---------------------------------------------------------------------------
extern "C" void kernel_launch(void* const* d_in, const int* in_sizes, int n_in,
                              void* d_out, int out_size)
{
    (void)in_sizes; (void)n_in; (void)out_size;
    const float* X  = (const float*)d_in[0];
    const float* Wq = (const float*)d_in[1];
    const float* Wk = (const float*)d_in[2];
    const float* Wv = (const float*)d_in[3];
    float* out = (float*)d_out;

    void *pXh, *pWqh, *pWkh, *pB2, *pRh, *pVh, *pVth, *pPh, *pL;
    cudaGetSymbolAddress(&pXh,  g_Xh);
    cudaGetSymbolAddress(&pWqh, g_Wqh);
    cudaGetSymbolAddress(&pWkh, g_Wkh);
    cudaGetSymbolAddress(&pB2,  g_B2);
    cudaGetSymbolAddress(&pRh,  g_Rh);
    cudaGetSymbolAddress(&pVh,  g_Vh);
    cudaGetSymbolAddress(&pVth, g_Vth);
    cudaGetSymbolAddress(&pPh,  g_Ph);
    cudaGetSymbolAddress(&pL,   g_invL);

    cudaFuncSetAttribute(h_gemm<0>, cudaFuncAttributeMaxDynamicSharedMemorySize, SMEM_BYTES);
    cudaFuncSetAttribute(h_gemm<1>, cudaFuncAttributeMaxDynamicSharedMemorySize, SMEM_BYTES);
    cudaFuncSetAttribute(h_gemm<2>, cudaFuncAttributeMaxDynamicSharedMemorySize, SMEM_BYTES);

    const float alpha = 0.036084391824351615f;   // 1/sqrt(768)

    round_x_kernel<<<3072, 256>>>(X);
    round_w_kernel<<<288, 256>>>(Wq, Wk);
    wtrans_v_kernel<<<dim3(24, 24), dim3(32, 8)>>>(Wv);

    // H = alpha * Wk · Wq^T  [768 x 768] (half), into g_B2[0]
    h_gemm<1><<<dim3(DD / 128, DD / 128, 1), 128, SMEM_BYTES>>>(
        (const __half*)pWkh, (const __half*)pWqh,
        pB2, nullptr, nullptr, nullptr,
        EE, DD, 0, 0, 0, alpha);

    // z=0: R = X · H^T-form (B=g_B2[0]) ; z=1: V = X · Wv (B=g_B2[1])
    h_gemm<0><<<dim3(EE / 128, BSROWS / 128, 2), 128, SMEM_BYTES>>>(
        (const __half*)pXh, (const __half*)pB2,
        pRh, pVh, pVh, nullptr,
        DD, EE, 0, (size_t)EE * DD, 0, 1.f);

    vtrans_kernel<<<dim3(24, 64, 8), dim3(32, 8)>>>();

    // sim = R[b] · X[b]^T  (alpha already folded into H), half out
    h_gemm<1><<<dim3(SS / 128, SS / 128, BB), 128, SMEM_BYTES>>>(
        (const __half*)pRh, (const __half*)pXh,
        pPh, nullptr, nullptr, nullptr,
        DD, SS, (size_t)SS * EE, (size_t)SS * DD, (size_t)SS * SS, 1.f);

    softmax_kernel<<<BSROWS, 256>>>();

    // out = P[b] · Vt[b]^T-form, scale invL, float out
    h_gemm<2><<<dim3(EE / 128, SS / 128, BB), 128, SMEM_BYTES>>>(
        (const __half*)pPh, (const __half*)pVth,
        out, nullptr, nullptr, (const float*)pL,
        SS, EE, (size_t)SS * SS, (size_t)SS * EE, (size_t)SS * EE, 1.f);
}